// round 5
// baseline (speedup 1.0000x reference)
#include <cuda_runtime.h>
#include <cuda_bf16.h>
#include <cstdint>

#define B_    4
#define C_    256
#define H_    128
#define W_    128
#define HW_   (H_*W_)
#define COMP_ 64
#define KK_   25
#define HO_   64
#define WO_   64

// Scratch (device globals; allocation is forbidden)
// g_comp layout: [b][px (h*W+w)][ch]  (channel-minor!)
__device__ float g_comp[B_*HW_*COMP_];
__device__ float g_mask[B_*KK_*HO_*WO_];
__device__ __align__(16) unsigned char g_w1b[COMP_*C_*2];   // w1 bf16, plain [n][k]

__device__ __forceinline__ uint32_t smem_u32(const void* p) {
    uint32_t a;
    asm("{ .reg .u64 t; cvta.to.shared.u64 t, %1; cvt.u32.u64 %0, t; }" : "=r"(a) : "l"(p));
    return a;
}

// ================= Kernel P: w1 fp32 -> bf16 =================
__global__ void k_prep(const float* __restrict__ w1) {
    int idx = blockIdx.x * 256 + threadIdx.x;
    if (idx < COMP_ * C_)
        ((__nv_bfloat16*)g_w1b)[idx] = __float2bfloat16(w1[idx]);
}

// ================= Kernel A: 1x1 conv via mma.sync bf16 =================
#define XS_OFF   0
#define WS_OFF   32768
#define BIAS_OFF 65536
#define A_SMEM_BYTES (65536 + 256)

__global__ __launch_bounds__(256) void k_conv1(const float* __restrict__ x,
                                               const float* __restrict__ b1) {
    extern __shared__ __align__(16) char sm[];
    const uint32_t smb = smem_u32(sm);
    const int tid  = threadIdx.x;
    const int warp = tid >> 5;
    const int lane = tid & 31;
    const int b    = blockIdx.y;
    const int px0  = blockIdx.x * 256;

    {
        const uint32_t* wsrc = (const uint32_t*)g_w1b;
        for (int i = tid; i < COMP_ * C_ / 2; i += 256) {
            int n = i >> 7, u = i & 127;
            int cx = u >> 2;
            uint32_t off = WS_OFF + n*512 + (uint32_t)((cx ^ (n & 7)) << 4) + (u & 3) * 4;
            *(uint32_t*)(sm + off) = wsrc[i];
        }
        if (tid < 64) ((float*)(sm + BIAS_OFF))[tid] = b1[tid];
    }

    float acc[2][8][4];
#pragma unroll
    for (int mt = 0; mt < 2; mt++)
#pragma unroll
        for (int nt = 0; nt < 8; nt++)
#pragma unroll
            for (int i = 0; i < 4; i++) acc[mt][nt][i] = 0.f;

    const int lj  = lane & 7;
    const int lg2 = (lane >> 3) & 1;
    const int lg4 = lane >> 4;
    const int g_  = lane >> 2;
    const int tig = lane & 3;

    const float* xbase = x + ((size_t)b * C_) * HW_ + px0;

    for (int chunk = 0; chunk < 4; chunk++) {
        __syncthreads();
        const float4* xsrc = (const float4*)(xbase + (size_t)(chunk * 64) * HW_);
#pragma unroll
        for (int l = 0; l < 16; l++) {
            int id = l * 256 + tid;
            int ch = id >> 6, f4 = id & 63;
            float4 v = xsrc[(size_t)ch * (HW_/4) + f4];
            __nv_bfloat162 h0 = __float22bfloat162_rn(make_float2(v.x, v.y));
            __nv_bfloat162 h1 = __float22bfloat162_rn(make_float2(v.z, v.w));
            int cx = f4 >> 1;
            uint32_t off = XS_OFF + ch*512 + (uint32_t)((cx ^ (ch & 7)) << 4) + (f4 & 1) * 8;
            *(uint2*)(sm + off) = make_uint2(*(uint32_t*)&h0, *(uint32_t*)&h1);
        }
        __syncthreads();

#pragma unroll
        for (int s = 0; s < 4; s++) {
            uint32_t a[2][4];
            const int krow = s*16 + lj + lg4*8;
#pragma unroll
            for (int mt = 0; mt < 2; mt++) {
                int pxcol = warp*32 + mt*16 + lg2*8;
                uint32_t addr = smb + XS_OFF + krow*512
                              + (uint32_t)(((pxcol >> 3) ^ (krow & 7)) << 4);
                asm volatile("ldmatrix.sync.aligned.m8n8.x4.trans.shared.b16 "
                             "{%0,%1,%2,%3}, [%4];"
                             : "=r"(a[mt][0]), "=r"(a[mt][1]), "=r"(a[mt][2]), "=r"(a[mt][3])
                             : "r"(addr));
            }
            const int kabs = chunk*64 + s*16;
            const int cx0  = kabs >> 3;
#pragma unroll
            for (int nt = 0; nt < 8; nt++) {
                int n = nt*8 + g_;
                uint32_t ab0 = smb + WS_OFF + n*512
                             + (uint32_t)(((cx0     ) ^ (n & 7)) << 4) + tig*4;
                uint32_t ab1 = smb + WS_OFF + n*512
                             + (uint32_t)(((cx0 + 1) ^ (n & 7)) << 4) + tig*4;
                uint32_t b0, b1v;
                asm volatile("ld.shared.b32 %0, [%1];" : "=r"(b0)  : "r"(ab0));
                asm volatile("ld.shared.b32 %0, [%1];" : "=r"(b1v) : "r"(ab1));
#pragma unroll
                for (int mt = 0; mt < 2; mt++) {
                    asm volatile(
                        "mma.sync.aligned.m16n8k16.row.col.f32.bf16.bf16.f32 "
                        "{%0,%1,%2,%3}, {%4,%5,%6,%7}, {%8,%9}, {%0,%1,%2,%3};"
                        : "+f"(acc[mt][nt][0]), "+f"(acc[mt][nt][1]),
                          "+f"(acc[mt][nt][2]), "+f"(acc[mt][nt][3])
                        : "r"(a[mt][0]), "r"(a[mt][1]), "r"(a[mt][2]), "r"(a[mt][3]),
                          "r"(b0), "r"(b1v));
                }
            }
        }
    }

    const float* bias = (const float*)(sm + BIAS_OFF);
#pragma unroll
    for (int mt = 0; mt < 2; mt++) {
        int px_a = px0 + warp*32 + mt*16 + g_;
#pragma unroll
        for (int nt = 0; nt < 8; nt++) {
            int n = nt*8 + tig*2;
            float bx = bias[n], by = bias[n+1];
            float* p0 = g_comp + ((size_t)b*HW_ + px_a) * COMP_ + n;
            *(float2*)p0             = make_float2(acc[mt][nt][0] + bx, acc[mt][nt][1] + by);
            *(float2*)(p0 + 8*COMP_) = make_float2(acc[mt][nt][2] + bx, acc[mt][nt][3] + by);
        }
    }
}

// ================= Kernel B: 3x3 stride-2 conv (64 -> 25) =================
#define CS_ROW   130
#define CS_CH    (5*CS_ROW)
#define B_SMEM_BYTES ((COMP_*CS_CH + KK_*COMP_*9) * 4)

__global__ __launch_bounds__(256) void k_conv2(const float* __restrict__ w2,
                                               const float* __restrict__ b2) {
    extern __shared__ __align__(16) float smemB[];
    float* cs  = smemB;
    float* w2s = smemB + COMP_*CS_CH;

    const int b   = blockIdx.y;
    const int hop = blockIdx.x;
    const int tid = threadIdx.x;

    for (int idx = tid; idx < KK_*COMP_*9; idx += 256) w2s[idx] = w2[idx];

    const int r0 = 4*hop - 1;
    for (int idx = tid; idx < COMP_*CS_CH; idx += 256) {
        int c   = idx & 63;
        int pix = idx >> 6;
        int r   = pix / CS_ROW;
        int col = pix - r*CS_ROW;
        int gr = r0 + r, gc = col - 1;
        float v = 0.f;
        if ((unsigned)gr < (unsigned)H_ && (unsigned)gc < (unsigned)W_)
            v = g_comp[((size_t)b*HW_ + gr*W_ + gc) * COMP_ + c];
        cs[c*CS_CH + r*CS_ROW + col] = v;
    }
    __syncthreads();

    const int wo = tid & 63;
    const int og = tid >> 6;
    const int nO = (og == 0) ? 7 : 6;

    float acc0[7], acc1[7];
#pragma unroll
    for (int t = 0; t < 7; t++) { acc0[t] = 0.f; acc1[t] = 0.f; }

#pragma unroll 1
    for (int c = 0; c < COMP_; c++) {
        float xv[5][3];
        const float* csp = cs + c*CS_CH + 2*wo;
#pragma unroll
        for (int r = 0; r < 5; r++)
#pragma unroll
            for (int j = 0; j < 3; j++)
                xv[r][j] = csp[r*CS_ROW + j];

#pragma unroll
        for (int t = 0; t < 7; t++) {
            if (t < nO) {
                int o = og + 4*t;
                const float* wp = w2s + o*(COMP_*9) + c*9;
#pragma unroll
                for (int ki = 0; ki < 3; ki++)
#pragma unroll
                    for (int kj = 0; kj < 3; kj++) {
                        float w = wp[ki*3 + kj];
                        acc0[t] = fmaf(w, xv[ki][kj],   acc0[t]);
                        acc1[t] = fmaf(w, xv[ki+2][kj], acc1[t]);
                    }
            }
        }
    }

    const int ho0 = 2*hop;
#pragma unroll
    for (int t = 0; t < 7; t++) {
        if (t < nO) {
            int o = og + 4*t;
            float bias = b2[o];
            g_mask[(((size_t)b*KK_ + o)*HO_ + ho0    )*WO_ + wo] = acc0[t] + bias;
            g_mask[(((size_t)b*KK_ + o)*HO_ + ho0 + 1)*WO_ + wo] = acc1[t] + bias;
        }
    }
}

// ================= Kernel C: softmax(25) + CARAFE via smem staging =================
// grid (64 ho, 8 cg(32ch), 4 b), block 256.
#define CXS   0
#define CMS   21120
#define CMST  22720
#define COS   25280
#define C_SMEM_BYTES (27360*4)

__global__ __launch_bounds__(256) void k_carafe(const float* __restrict__ x,
                                                float* __restrict__ out) {
    extern __shared__ __align__(16) float smc[];
    float* xs  = smc + CXS;
    float* ms  = smc + CMS;
    float* msT = smc + CMST;
    float* os  = smc + COS;

    const int ho  = blockIdx.x;
    const int cg  = blockIdx.y;
    const int b   = blockIdx.z;
    const int tid = threadIdx.x;
    const int ch0 = cg * 32;

    // ---- load mask logits (coalesced) ----
    for (int idx = tid; idx < KK_*64; idx += 256)
        ms[idx] = g_mask[(((size_t)b*KK_ + (idx >> 6))*HO_ + ho)*WO_ + (idx & 63)];

    // ---- load x footprint: 32 ch x 5 rows x 128 cols -> xs padded [132] ----
    const int r0 = 2*ho - 2;
    {
        const float2* x2 = (const float2*)(x + ((size_t)b*C_ + ch0) * HW_);
        const float2 z2 = make_float2(0.f, 0.f);
        for (int idx = tid; idx < 32*5*64; idx += 256) {
            int ch  = idx / 320;
            int rem = idx - ch*320;
            int r   = rem >> 6;
            int u   = rem & 63;
            int gr  = r0 + r;
            float2 v = ((unsigned)gr < (unsigned)H_)
                     ? __ldg(x2 + (size_t)ch*(HW_/2) + gr*(W_/2) + u) : z2;
            *(float2*)&xs[ch*660 + r*132 + 2 + 2*u] = v;
        }
        // pads: 32*5*2 = 320 float2 (cols 0-1 and 130-131) -- FIX: grid-stride loop
        for (int idx = tid; idx < 320; idx += 256) {
            int ch = idx / 10;
            int rem = idx - ch*10;
            int r = rem >> 1, side = rem & 1;
            *(float2*)&xs[ch*660 + r*132 + side*130] = z2;
        }
    }
    __syncthreads();

    // ---- softmax over 25, write transposed msT[wo][i][8] ----
    if (tid < 64) {
        float mx = -1e30f;
#pragma unroll
        for (int o = 0; o < KK_; o++) mx = fmaxf(mx, ms[o*64 + tid]);
        float e[KK_]; float s = 0.f;
#pragma unroll
        for (int o = 0; o < KK_; o++) { e[o] = __expf(ms[o*64 + tid] - mx); s += e[o]; }
        float inv = 1.f / s;
#pragma unroll
        for (int o = 0; o < KK_; o++)
            msT[tid*40 + (o/5)*8 + (o%5)] = e[o] * inv;
    }
    __syncthreads();

    // ---- compute: warp = output octet, lane = channel ----
    const int oct  = tid >> 5;
    const int lch  = tid & 31;
    const float* xw = xs + lch*660 + 16*oct;
    const float* wt = msT + (8*oct)*40;

    float acc[8];
#pragma unroll
    for (int k = 0; k < 8; k++) acc[k] = 0.f;

#pragma unroll
    for (int i = 0; i < 5; i++) {
        float4 v0 = *(const float4*)(xw + i*132 + 0);
        float4 v1 = *(const float4*)(xw + i*132 + 4);
        float4 v2 = *(const float4*)(xw + i*132 + 8);
        float4 v3 = *(const float4*)(xw + i*132 + 12);
        float4 v4 = *(const float4*)(xw + i*132 + 16);
        float v[20] = { v0.x,v0.y,v0.z,v0.w, v1.x,v1.y,v1.z,v1.w,
                        v2.x,v2.y,v2.z,v2.w, v3.x,v3.y,v3.z,v3.w,
                        v4.x,v4.y,v4.z,v4.w };
#pragma unroll
        for (int k = 0; k < 8; k++) {
            float4 w4 = *(const float4*)(wt + k*40 + i*8);
            float  w5 = wt[k*40 + i*8 + 4];
            float a = acc[k];
            a = fmaf(w4.x, v[2*k + 0], a);
            a = fmaf(w4.y, v[2*k + 1], a);
            a = fmaf(w4.z, v[2*k + 2], a);
            a = fmaf(w4.w, v[2*k + 3], a);
            a = fmaf(w5,   v[2*k + 4], a);
            acc[k] = a;
        }
    }

    // ---- stage outputs in smem (conflict-free), then coalesced STG ----
#pragma unroll
    for (int k = 0; k < 8; k++) os[lch*65 + 8*oct + k] = acc[k];
    __syncthreads();

    float* ob = out + (((size_t)b*C_ + ch0)*HO_ + ho)*WO_;
#pragma unroll
    for (int l = 0; l < 8; l++) {
        int idx = l*256 + tid;
        int ch = idx >> 6, wo = idx & 63;
        ob[(size_t)ch*HO_*WO_ + wo] = os[ch*65 + wo];
    }
}

// ================= launch =================
extern "C" void kernel_launch(void* const* d_in, const int* in_sizes, int n_in,
                              void* d_out, int out_size) {
    const float* x  = (const float*)d_in[0];
    const float* w1 = (const float*)d_in[1];
    const float* b1 = (const float*)d_in[2];
    const float* w2 = (const float*)d_in[3];
    const float* b2 = (const float*)d_in[4];
    float* out = (float*)d_out;

    cudaFuncSetAttribute(k_conv1,  cudaFuncAttributeMaxDynamicSharedMemorySize, A_SMEM_BYTES);
    cudaFuncSetAttribute(k_conv2,  cudaFuncAttributeMaxDynamicSharedMemorySize, B_SMEM_BYTES);
    cudaFuncSetAttribute(k_carafe, cudaFuncAttributeMaxDynamicSharedMemorySize, C_SMEM_BYTES);

    k_prep<<<64, 256>>>(w1);
    k_conv1<<<dim3(64, 4), 256, A_SMEM_BYTES>>>(x, b1);
    k_conv2<<<dim3(32, 4), 256, B_SMEM_BYTES>>>(w2, b2);
    k_carafe<<<dim3(64, 8, 4), 256, C_SMEM_BYTES>>>(x, out);
}

// round 6
// speedup vs baseline: 1.1994x; 1.1994x over previous
#include <cuda_runtime.h>
#include <cuda_bf16.h>
#include <cstdint>

#define B_    4
#define C_    256
#define H_    128
#define W_    128
#define HW_   (H_*W_)
#define COMP_ 64
#define KK_   25
#define HO_   64
#define WO_   64

// Scratch (device globals; allocation is forbidden)
// g_comp layout: [b][px (h*W+w)][ch]  (channel-minor!)
__device__ float g_comp[B_*HW_*COMP_];
__device__ float g_mask[B_*KK_*HO_*WO_];                    // NORMALIZED softmax weights
__device__ __align__(16) unsigned char g_w1b[COMP_*C_*2];   // w1 bf16, plain [n][k]

__device__ __forceinline__ uint32_t smem_u32(const void* p) {
    uint32_t a;
    asm("{ .reg .u64 t; cvta.to.shared.u64 t, %1; cvt.u32.u64 %0, t; }" : "=r"(a) : "l"(p));
    return a;
}

// ================= Kernel P: w1 fp32 -> bf16 =================
__global__ void k_prep(const float* __restrict__ w1) {
    int idx = blockIdx.x * 256 + threadIdx.x;
    if (idx < COMP_ * C_)
        ((__nv_bfloat16*)g_w1b)[idx] = __float2bfloat16(w1[idx]);
}

// ================= Kernel A: 1x1 conv via mma.sync bf16 =================
#define XS_OFF   0
#define WS_OFF   32768
#define BIAS_OFF 65536
#define A_SMEM_BYTES (65536 + 256)

__global__ __launch_bounds__(256) void k_conv1(const float* __restrict__ x,
                                               const float* __restrict__ b1) {
    extern __shared__ __align__(16) char sm[];
    const uint32_t smb = smem_u32(sm);
    const int tid  = threadIdx.x;
    const int warp = tid >> 5;
    const int lane = tid & 31;
    const int b    = blockIdx.y;
    const int px0  = blockIdx.x * 256;

    {
        const uint32_t* wsrc = (const uint32_t*)g_w1b;
        for (int i = tid; i < COMP_ * C_ / 2; i += 256) {
            int n = i >> 7, u = i & 127;
            int cx = u >> 2;
            uint32_t off = WS_OFF + n*512 + (uint32_t)((cx ^ (n & 7)) << 4) + (u & 3) * 4;
            *(uint32_t*)(sm + off) = wsrc[i];
        }
        if (tid < 64) ((float*)(sm + BIAS_OFF))[tid] = b1[tid];
    }

    float acc[2][8][4];
#pragma unroll
    for (int mt = 0; mt < 2; mt++)
#pragma unroll
        for (int nt = 0; nt < 8; nt++)
#pragma unroll
            for (int i = 0; i < 4; i++) acc[mt][nt][i] = 0.f;

    const int lj  = lane & 7;
    const int lg2 = (lane >> 3) & 1;
    const int lg4 = lane >> 4;
    const int g_  = lane >> 2;
    const int tig = lane & 3;

    const float* xbase = x + ((size_t)b * C_) * HW_ + px0;

    for (int chunk = 0; chunk < 4; chunk++) {
        __syncthreads();
        const float4* xsrc = (const float4*)(xbase + (size_t)(chunk * 64) * HW_);
#pragma unroll
        for (int l = 0; l < 16; l++) {
            int id = l * 256 + tid;
            int ch = id >> 6, f4 = id & 63;
            float4 v = xsrc[(size_t)ch * (HW_/4) + f4];
            __nv_bfloat162 h0 = __float22bfloat162_rn(make_float2(v.x, v.y));
            __nv_bfloat162 h1 = __float22bfloat162_rn(make_float2(v.z, v.w));
            int cx = f4 >> 1;
            uint32_t off = XS_OFF + ch*512 + (uint32_t)((cx ^ (ch & 7)) << 4) + (f4 & 1) * 8;
            *(uint2*)(sm + off) = make_uint2(*(uint32_t*)&h0, *(uint32_t*)&h1);
        }
        __syncthreads();

#pragma unroll
        for (int s = 0; s < 4; s++) {
            uint32_t a[2][4];
            const int krow = s*16 + lj + lg4*8;
#pragma unroll
            for (int mt = 0; mt < 2; mt++) {
                int pxcol = warp*32 + mt*16 + lg2*8;
                uint32_t addr = smb + XS_OFF + krow*512
                              + (uint32_t)(((pxcol >> 3) ^ (krow & 7)) << 4);
                asm volatile("ldmatrix.sync.aligned.m8n8.x4.trans.shared.b16 "
                             "{%0,%1,%2,%3}, [%4];"
                             : "=r"(a[mt][0]), "=r"(a[mt][1]), "=r"(a[mt][2]), "=r"(a[mt][3])
                             : "r"(addr));
            }
            const int kabs = chunk*64 + s*16;
            const int cx0  = kabs >> 3;
#pragma unroll
            for (int nt = 0; nt < 8; nt++) {
                int n = nt*8 + g_;
                uint32_t ab0 = smb + WS_OFF + n*512
                             + (uint32_t)(((cx0     ) ^ (n & 7)) << 4) + tig*4;
                uint32_t ab1 = smb + WS_OFF + n*512
                             + (uint32_t)(((cx0 + 1) ^ (n & 7)) << 4) + tig*4;
                uint32_t b0, b1v;
                asm volatile("ld.shared.b32 %0, [%1];" : "=r"(b0)  : "r"(ab0));
                asm volatile("ld.shared.b32 %0, [%1];" : "=r"(b1v) : "r"(ab1));
#pragma unroll
                for (int mt = 0; mt < 2; mt++) {
                    asm volatile(
                        "mma.sync.aligned.m16n8k16.row.col.f32.bf16.bf16.f32 "
                        "{%0,%1,%2,%3}, {%4,%5,%6,%7}, {%8,%9}, {%0,%1,%2,%3};"
                        : "+f"(acc[mt][nt][0]), "+f"(acc[mt][nt][1]),
                          "+f"(acc[mt][nt][2]), "+f"(acc[mt][nt][3])
                        : "r"(a[mt][0]), "r"(a[mt][1]), "r"(a[mt][2]), "r"(a[mt][3]),
                          "r"(b0), "r"(b1v));
                }
            }
        }
    }

    const float* bias = (const float*)(sm + BIAS_OFF);
#pragma unroll
    for (int mt = 0; mt < 2; mt++) {
        int px_a = px0 + warp*32 + mt*16 + g_;
#pragma unroll
        for (int nt = 0; nt < 8; nt++) {
            int n = nt*8 + tig*2;
            float bx = bias[n], by = bias[n+1];
            float* p0 = g_comp + ((size_t)b*HW_ + px_a) * COMP_ + n;
            *(float2*)p0             = make_float2(acc[mt][nt][0] + bx, acc[mt][nt][1] + by);
            *(float2*)(p0 + 8*COMP_) = make_float2(acc[mt][nt][2] + bx, acc[mt][nt][3] + by);
        }
    }
}

// ================= Kernel B: 3x3 stride-2 conv (64 -> 25) + fused softmax =================
// smem: cs [64][5][130] (166.4KB) | wA [25][64][8] (51.2KB) | wB [25][64] (6.4KB)
// softmax staging ls reuses the cs region after compute. ls pad 29 (conflict-free).
#define CS_ROW   130
#define CS_CH    (5*CS_ROW)
#define WA_OFF   (COMP_*CS_CH)                 // floats
#define WB_OFF   (WA_OFF + KK_*COMP_*8)
#define B_SMEM_FLOATS (WB_OFF + KK_*COMP_)
#define B_SMEM_BYTES (B_SMEM_FLOATS*4)

__global__ __launch_bounds__(256) void k_conv2(const float* __restrict__ w2,
                                               const float* __restrict__ b2) {
    extern __shared__ __align__(16) float smemB[];
    float* cs = smemB;
    float* wA = smemB + WA_OFF;
    float* wB = smemB + WB_OFF;
    float* ls = smemB;                          // reused after compute: [128][29]

    const int b   = blockIdx.y;
    const int hop = blockIdx.x;
    const int tid = threadIdx.x;

    // weights: split 8+1 for aligned float4 loads
    for (int idx = tid; idx < KK_*COMP_*8; idx += 256) {
        int oc = idx >> 3, k = idx & 7;
        wA[idx] = w2[oc*9 + k];
    }
    for (int idx = tid; idx < KK_*COMP_; idx += 256)
        wB[idx] = w2[idx*9 + 8];

    const int r0 = 4*hop - 1;
    for (int idx = tid; idx < COMP_*CS_CH; idx += 256) {
        int c   = idx & 63;
        int pix = idx >> 6;
        int r   = pix / CS_ROW;
        int col = pix - r*CS_ROW;
        int gr = r0 + r, gc = col - 1;
        float v = 0.f;
        if ((unsigned)gr < (unsigned)H_ && (unsigned)gc < (unsigned)W_)
            v = g_comp[((size_t)b*HW_ + gr*W_ + gc) * COMP_ + c];
        cs[c*CS_CH + r*CS_ROW + col] = v;
    }
    __syncthreads();

    const int wo = tid & 63;
    const int og = tid >> 6;
    const int nO = (og == 0) ? 7 : 6;

    float acc0[7], acc1[7];
#pragma unroll
    for (int t = 0; t < 7; t++) { acc0[t] = 0.f; acc1[t] = 0.f; }

#pragma unroll 1
    for (int c = 0; c < COMP_; c++) {
        const float* csp = cs + c*CS_CH + 2*wo;
        float xv[5][3];
#pragma unroll
        for (int r = 0; r < 5; r++) {
            float2 u = *(const float2*)(csp + r*CS_ROW);
            xv[r][0] = u.x; xv[r][1] = u.y;
            xv[r][2] = csp[r*CS_ROW + 2];
        }
#pragma unroll
        for (int t = 0; t < 7; t++) {
            if (t < nO) {
                int o = og + 4*t;
                const float* wa = wA + (o*COMP_ + c)*8;
                float4 v0 = *(const float4*)wa;
                float4 v1 = *(const float4*)(wa + 4);
                float  w8 = wB[o*COMP_ + c];
                float a0 = acc0[t], a1 = acc1[t];
                a0 = fmaf(v0.x, xv[0][0], a0);  a1 = fmaf(v0.x, xv[2][0], a1);
                a0 = fmaf(v0.y, xv[0][1], a0);  a1 = fmaf(v0.y, xv[2][1], a1);
                a0 = fmaf(v0.z, xv[0][2], a0);  a1 = fmaf(v0.z, xv[2][2], a1);
                a0 = fmaf(v0.w, xv[1][0], a0);  a1 = fmaf(v0.w, xv[3][0], a1);
                a0 = fmaf(v1.x, xv[1][1], a0);  a1 = fmaf(v1.x, xv[3][1], a1);
                a0 = fmaf(v1.y, xv[1][2], a0);  a1 = fmaf(v1.y, xv[3][2], a1);
                a0 = fmaf(v1.z, xv[2][0], a0);  a1 = fmaf(v1.z, xv[4][0], a1);
                a0 = fmaf(v1.w, xv[2][1], a0);  a1 = fmaf(v1.w, xv[4][1], a1);
                a0 = fmaf(w8,   xv[2][2], a0);  a1 = fmaf(w8,   xv[4][2], a1);
                acc0[t] = a0; acc1[t] = a1;
            }
        }
    }

    // ---- stage logits (+bias) into ls[128][29], then fused softmax ----
    __syncthreads();        // cs reads done; safe to reuse region as ls
#pragma unroll
    for (int t = 0; t < 7; t++) {
        if (t < nO) {
            int o = og + 4*t;
            float bias = b2[o];
            ls[(     wo)*29 + o] = acc0[t] + bias;
            ls[(64 + wo)*29 + o] = acc1[t] + bias;
        }
    }
    __syncthreads();

    const int ho0 = 2*hop;
    if (tid < 128) {
        const float* lp = ls + tid*29;
        float mx = -1e30f;
#pragma unroll
        for (int o = 0; o < KK_; o++) mx = fmaxf(mx, lp[o]);
        float e[KK_]; float s = 0.f;
#pragma unroll
        for (int o = 0; o < KK_; o++) { e[o] = __expf(lp[o] - mx); s += e[o]; }
        float inv = 1.f / s;
        int ho = ho0 + (tid >> 6);
        int wx = tid & 63;
#pragma unroll
        for (int o = 0; o < KK_; o++)
            g_mask[(((size_t)b*KK_ + o)*HO_ + ho)*WO_ + wx] = e[o] * inv;
    }
}

// ================= Kernel C: CARAFE gather (normalized weights, LDG.128 windows) =================
// grid (64 ho, 4 cq, 4 b), block 256. Thread = (wo-pair p, 8-channel slot).
__global__ __launch_bounds__(256) void k_carafe(const float* __restrict__ x,
                                                float* __restrict__ out) {
    __shared__ float ms[KK_*64];

    const int ho = blockIdx.x;
    const int cq = blockIdx.y;
    const int b  = blockIdx.z;
    const int tid = threadIdx.x;

    for (int idx = tid; idx < KK_*64; idx += 256)
        ms[idx] = g_mask[(((size_t)b*KK_ + (idx >> 6))*HO_ + ho)*WO_ + (idx & 63)];
    __syncthreads();

    const int p    = tid & 31;   // output pair 2p, 2p+1
    const int slot = tid >> 5;

    float mw0[KK_], mw1[KK_];
#pragma unroll
    for (int o = 0; o < KK_; o++) { mw0[o] = ms[o*64 + 2*p]; mw1[o] = ms[o*64 + 2*p + 1]; }

    const int r0 = 2*ho - 2;
    const bool okL = (p > 0);
    const bool okR = (p < 31);
    const float4 z4 = make_float4(0.f, 0.f, 0.f, 0.f);

#pragma unroll 1
    for (int t = 0; t < 8; t++) {
        const int c = cq*64 + slot*8 + t;
        const float* xc = x + ((size_t)(b*C_ + c)) * HW_ + 4*p;
        float a0 = 0.f, a1 = 0.f;
#pragma unroll
        for (int i = 0; i < 5; i++) {
            const int r = r0 + i;
            if ((unsigned)r < (unsigned)H_) {
                const float* base = xc + (size_t)r*W_;
                float4 L1 = __ldg((const float4*)base);              // cols 4p..4p+3
                float4 L0 = okL ? __ldg((const float4*)(base - 4)) : z4;  // 4p-4..4p-1
                float4 L2 = okR ? __ldg((const float4*)(base + 4)) : z4;  // 4p+4..4p+7
                // pixel 2p: cols 4p-2..4p+2 ; pixel 2p+1: cols 4p..4p+4
                a0 = fmaf(mw0[5*i+0], L0.z, a0);
                a0 = fmaf(mw0[5*i+1], L0.w, a0);
                a0 = fmaf(mw0[5*i+2], L1.x, a0);
                a0 = fmaf(mw0[5*i+3], L1.y, a0);
                a0 = fmaf(mw0[5*i+4], L1.z, a0);
                a1 = fmaf(mw1[5*i+0], L1.x, a1);
                a1 = fmaf(mw1[5*i+1], L1.y, a1);
                a1 = fmaf(mw1[5*i+2], L1.z, a1);
                a1 = fmaf(mw1[5*i+3], L1.w, a1);
                a1 = fmaf(mw1[5*i+4], L2.x, a1);
            }
        }
        *(float2*)&out[(((size_t)b*C_ + c)*HO_ + ho)*WO_ + 2*p] = make_float2(a0, a1);
    }
}

// ================= launch =================
extern "C" void kernel_launch(void* const* d_in, const int* in_sizes, int n_in,
                              void* d_out, int out_size) {
    const float* x  = (const float*)d_in[0];
    const float* w1 = (const float*)d_in[1];
    const float* b1 = (const float*)d_in[2];
    const float* w2 = (const float*)d_in[3];
    const float* b2 = (const float*)d_in[4];
    float* out = (float*)d_out;

    cudaFuncSetAttribute(k_conv1, cudaFuncAttributeMaxDynamicSharedMemorySize, A_SMEM_BYTES);
    cudaFuncSetAttribute(k_conv2, cudaFuncAttributeMaxDynamicSharedMemorySize, B_SMEM_BYTES);

    k_prep<<<64, 256>>>(w1);
    k_conv1<<<dim3(64, 4), 256, A_SMEM_BYTES>>>(x, b1);
    k_conv2<<<dim3(32, 4), 256, B_SMEM_BYTES>>>(w2, b2);
    k_carafe<<<dim3(64, 4, 4), 256>>>(x, out);
}